// round 5
// baseline (speedup 1.0000x reference)
#include <cuda_runtime.h>
#include <math.h>

#define NB 4
#define NN 2048
#define FIN 32
#define DD 64
#define MAXNB 512
#define ROWS (NB*NN)

// ---------------- scratch (device globals; no allocation allowed) ----------
__device__ int   g_cnt[NN];
__device__ int   g_cols[NN*MAXNB];
__device__ float g_proj[ROWS*DD];
__device__ float g_q1[ROWS*128];
__device__ float g_k1[ROWS*128];
__device__ float g_v1[ROWS*128];
__device__ float g_h1[ROWS*128];
__device__ float g_q2[ROWS*64];
__device__ float g_k2[ROWS*64];
__device__ float g_v2[ROWS*64];

// ---------------- kernel 1: deterministic CSR build ------------------------
__global__ __launch_bounds__(256, 4)
void build_csr(const float* __restrict__ adj) {
    int r = blockIdx.x;               // node row
    int t = threadIdx.x;              // 256 threads
    int w = t >> 5, l = t & 31;
    __shared__ int wcnt[8];
    int base = 0;
    for (int c0 = 0; c0 < NN; c0 += 256) {
        int col = c0 + t;
        bool pred = (adj[r*NN + col] != 0.0f);
        unsigned m = __ballot_sync(0xffffffffu, pred);
        if (l == 0) wcnt[w] = __popc(m);
        __syncthreads();
        int pre = 0, tot = 0;
        #pragma unroll
        for (int k = 0; k < 8; k++) { if (k < w) pre += wcnt[k]; tot += wcnt[k]; }
        int pos = base + pre + __popc(m & ((1u << l) - 1u));
        if (pred && pos < MAXNB) g_cols[r*MAXNB + pos] = col;
        base += tot;
        __syncthreads();
    }
    if (t == 0) g_cnt[r] = (base < MAXNB) ? base : MAXNB;
}

// ---------------- kernel 2: fused linear1 (proj + q1/k1/v1), 16 rows/block --
#define RPB1 16
__global__ __launch_bounds__(448, 2)
void linear1(const float* __restrict__ x,
             const float* __restrict__ Wp,  const float* __restrict__ bp,
             const float* __restrict__ Wq1, const float* __restrict__ bq1,
             const float* __restrict__ Wk1, const float* __restrict__ bk1,
             const float* __restrict__ Wv1, const float* __restrict__ bv1) {
    int row0 = blockIdx.x * RPB1;
    int t = threadIdx.x;              // 448
    __shared__ float xs[RPB1*FIN];
    // 16*32 floats = 128 float4
    for (int i = t; i < RPB1*FIN/4; i += 448)
        ((float4*)xs)[i] = ((const float4*)(x + row0*FIN))[i];
    __syncthreads();

    const float* W; const float* bi; float* dst; int c, nc;
    if (t < 64)        { W = Wp;  bi = bp;  dst = g_proj; c = t;       nc = 64;  }
    else if (t < 192)  { W = Wq1; bi = bq1; dst = g_q1;   c = t - 64;  nc = 128; }
    else if (t < 320)  { W = Wk1; bi = bk1; dst = g_k1;   c = t - 192; nc = 128; }
    else               { W = Wv1; bi = bv1; dst = g_v1;   c = t - 320; nc = 128; }

    float acc[RPB1];
    float bv = bi[c];
    #pragma unroll
    for (int r = 0; r < RPB1; r++) acc[r] = bv;
    #pragma unroll
    for (int k = 0; k < FIN; k++) {
        float wv = W[k*nc + c];
        #pragma unroll
        for (int r = 0; r < RPB1; r++) acc[r] += xs[r*FIN + k] * wv;
    }
    #pragma unroll
    for (int r = 0; r < RPB1; r++) dst[(row0 + r)*nc + c] = acc[r];
}

// ---------------- kernel 3: GAT1 sparse attention (4 heads, d=32) ----------
__global__ __launch_bounds__(128, 8)
void gat1(void) {
    int row = blockIdx.x;             // b*N+i
    int b = row >> 11, i = row & (NN - 1);
    int t = threadIdx.x;              // 128
    int w = t >> 5, l = t & 31;

    __shared__ float sc[4*MAXNB];
    __shared__ int   cols_s[MAXNB];
    __shared__ float m_run[4], l_run[4], factor_s[4];

    // lane l covers dims 4l..4l+3 (head = l>>3)
    float4 q4 = __ldg(((const float4*)(g_q1 + row*128)) + l);
    if (t < 4) { m_run[t] = -1e30f; l_run[t] = 0.0f; }

    int cnt = g_cnt[i];
    bool dense = (cnt == 0);
    int total = dense ? NN : cnt;
    const float SC1 = 0.17677669529663689f;  // 1/sqrt(32)
    float acc = 0.0f;

    for (int cs = 0; cs < total; cs += MAXNB) {
        int clen = min(MAXNB, total - cs);
        for (int idx = t; idx < clen; idx += 128)
            cols_s[idx] = dense ? (cs + idx) : g_cols[i*MAXNB + cs + idx];
        __syncthreads();

        // phase A: warp w handles neighbors w, w+4, ...; 4 heads via 8-lane segments
        #pragma unroll 2
        for (int idx = w; idx < clen; idx += 4) {
            const float4* kr = (const float4*)(g_k1 + (b*NN + cols_s[idx])*128);
            float4 k4 = __ldg(kr + l);
            float p = q4.x*k4.x + q4.y*k4.y + q4.z*k4.z + q4.w*k4.w;
            p += __shfl_down_sync(0xffffffffu, p, 4);
            p += __shfl_down_sync(0xffffffffu, p, 2);
            p += __shfl_down_sync(0xffffffffu, p, 1);
            if ((l & 7) == 0) sc[(l >> 3)*MAXNB + idx] = p * SC1;
        }
        __syncthreads();

        // phase B1: warp w = head w online-softmax stats
        {
            float mc = -1e30f;
            for (int idx = l; idx < clen; idx += 32)
                mc = fmaxf(mc, sc[w*MAXNB + idx]);
            #pragma unroll
            for (int off = 16; off; off >>= 1)
                mc = fmaxf(mc, __shfl_xor_sync(0xffffffffu, mc, off));
            float mo = m_run[w];
            float mn = fmaxf(mo, mc);
            float f  = __expf(mo - mn);
            float ls = 0.0f;
            for (int idx = l; idx < clen; idx += 32) {
                float p = __expf(sc[w*MAXNB + idx] - mn);
                sc[w*MAXNB + idx] = p;
                ls += p;
            }
            #pragma unroll
            for (int off = 16; off; off >>= 1)
                ls += __shfl_xor_sync(0xffffffffu, ls, off);
            if (l == 0) { m_run[w] = mn; l_run[w] = l_run[w]*f + ls; factor_s[w] = f; }
        }
        __syncthreads();

        // phase B2: thread t accumulates output dim t; 4-deep manual MLP
        {
            float f = factor_s[w];
            acc *= f;
            const float* vb = g_v1 + b*NN*128 + t;
            const float* scw = sc + w*MAXNB;
            int idx = 0;
            for (; idx + 4 <= clen; idx += 4) {
                int c0 = cols_s[idx], c1 = cols_s[idx+1];
                int c2 = cols_s[idx+2], c3 = cols_s[idx+3];
                float v0 = __ldg(vb + c0*128), v1 = __ldg(vb + c1*128);
                float v2 = __ldg(vb + c2*128), v3 = __ldg(vb + c3*128);
                acc += scw[idx]*v0 + scw[idx+1]*v1 + scw[idx+2]*v2 + scw[idx+3]*v3;
            }
            for (; idx < clen; idx++)
                acc += scw[idx] * __ldg(vb + cols_s[idx]*128);
        }
        __syncthreads();
    }
    g_h1[row*128 + t] = acc / l_run[w];
}

// ---------------- kernel 4: linear2 with fused ReLU, 16 rows/block ----------
#define RPB2 16
__global__ __launch_bounds__(192, 4)
void linear2(const float* __restrict__ Wq2, const float* __restrict__ bq2,
             const float* __restrict__ Wk2, const float* __restrict__ bk2,
             const float* __restrict__ Wv2, const float* __restrict__ bv2) {
    int row0 = blockIdx.x * RPB2;
    int t = threadIdx.x;              // 192
    __shared__ float hs[RPB2*128];
    // 16*128 floats = 512 float4; fused ReLU
    for (int i = t; i < RPB2*128/4; i += 192) {
        float4 v = ((const float4*)(g_h1 + row0*128))[i];
        v.x = fmaxf(v.x, 0.0f); v.y = fmaxf(v.y, 0.0f);
        v.z = fmaxf(v.z, 0.0f); v.w = fmaxf(v.w, 0.0f);
        ((float4*)hs)[i] = v;
    }
    __syncthreads();

    int c = t & 63;
    int g = t >> 6;                   // 0=q2, 1=k2, 2=v2
    const float* W; const float* bi; float* dst;
    if (g == 0)      { W = Wq2; bi = bq2; dst = g_q2; }
    else if (g == 1) { W = Wk2; bi = bk2; dst = g_k2; }
    else             { W = Wv2; bi = bv2; dst = g_v2; }

    float acc[RPB2];
    float bv = bi[c];
    #pragma unroll
    for (int r = 0; r < RPB2; r++) acc[r] = bv;
    #pragma unroll 4
    for (int k = 0; k < 128; k++) {
        float wv = W[k*64 + c];
        #pragma unroll
        for (int r = 0; r < RPB2; r++) acc[r] += hs[r*128 + k] * wv;
    }
    #pragma unroll
    for (int r = 0; r < RPB2; r++) dst[(row0 + r)*64 + c] = acc[r];
}

// ---------------- kernel 5: GAT2 (1 head, d=64) + residual + LayerNorm ------
__global__ __launch_bounds__(128, 8)
void gat2_ln(const float* __restrict__ gamma, const float* __restrict__ beta,
             float* __restrict__ out) {
    int row = blockIdx.x;             // b*N+i
    int b = row >> 11, i = row & (NN - 1);
    int t = threadIdx.x;              // 128
    int w = t >> 5, l = t & 31;
    int sub = l >> 4, ll = l & 15;    // 16-lane segments for scores
    int grp = t >> 6, d = t & 63;     // 2 neighbor-groups for V accumulation

    __shared__ float sc[MAXNB];
    __shared__ int   cols_s[MAXNB];
    __shared__ float m_run, l_run, factor_s;
    __shared__ float accs[128];
    __shared__ float red[4];

    // lane ll covers dims 4*ll..4*ll+3 of q (64 dims over 16 lanes)
    float4 q4 = __ldg(((const float4*)(g_q2 + row*64)) + ll);
    if (t == 0) { m_run = -1e30f; l_run = 0.0f; }

    int cnt = g_cnt[i];
    bool dense = (cnt == 0);
    int total = dense ? NN : cnt;
    float acc = 0.0f;

    for (int cs = 0; cs < total; cs += MAXNB) {
        int clen = min(MAXNB, total - cs);
        for (int idx = t; idx < clen; idx += 128)
            cols_s[idx] = dense ? (cs + idx) : g_cols[i*MAXNB + cs + idx];
        __syncthreads();

        // phase A: 8 neighbors per iteration (4 warps x 2 per warp)
        #pragma unroll 2
        for (int bidx = w*2; bidx < clen; bidx += 8) {
            int idx = bidx + sub;
            float p = 0.0f;
            if (idx < clen) {
                const float4* kr = (const float4*)(g_k2 + (b*NN + cols_s[idx])*64);
                float4 k4 = __ldg(kr + ll);
                p = q4.x*k4.x + q4.y*k4.y + q4.z*k4.z + q4.w*k4.w;
            }
            p += __shfl_down_sync(0xffffffffu, p, 8);
            p += __shfl_down_sync(0xffffffffu, p, 4);
            p += __shfl_down_sync(0xffffffffu, p, 2);
            p += __shfl_down_sync(0xffffffffu, p, 1);
            if (ll == 0 && idx < clen) sc[idx] = p * 0.125f;   // 1/sqrt(64)
        }
        __syncthreads();

        // phase B1: warp 0 online softmax stats
        if (w == 0) {
            float mc = -1e30f;
            for (int idx = l; idx < clen; idx += 32) mc = fmaxf(mc, sc[idx]);
            #pragma unroll
            for (int off = 16; off; off >>= 1)
                mc = fmaxf(mc, __shfl_xor_sync(0xffffffffu, mc, off));
            float mo = m_run;
            float mn = fmaxf(mo, mc);
            float f  = __expf(mo - mn);
            float ls = 0.0f;
            for (int idx = l; idx < clen; idx += 32) {
                float p = __expf(sc[idx] - mn);
                sc[idx] = p;
                ls += p;
            }
            #pragma unroll
            for (int off = 16; off; off >>= 1)
                ls += __shfl_xor_sync(0xffffffffu, ls, off);
            if (l == 0) { m_run = mn; l_run = l_run*f + ls; factor_s = f; }
        }
        __syncthreads();

        // phase B2: two 64-thread groups split neighbors (even/odd); MLP-4
        {
            float f = factor_s;
            acc *= f;
            const float* vb = g_v2 + b*NN*64 + d;
            int idx = grp;
            for (; idx + 8 <= clen + grp; idx += 8) {
                int c0 = cols_s[idx], c1 = cols_s[idx+2];
                int c2 = cols_s[idx+4], c3 = cols_s[idx+6];
                float v0 = __ldg(vb + c0*64), v1 = __ldg(vb + c1*64);
                float v2 = __ldg(vb + c2*64), v3 = __ldg(vb + c3*64);
                acc += sc[idx]*v0 + sc[idx+2]*v1 + sc[idx+4]*v2 + sc[idx+6]*v3;
            }
            for (; idx < clen; idx += 2)
                acc += sc[idx] * __ldg(vb + cols_s[idx]*64);
        }
        __syncthreads();
    }

    accs[t] = acc;
    __syncthreads();

    // residual + LayerNorm over 64
    float y = 0.0f;
    if (t < 64) {
        y = (accs[t] + accs[t + 64]) / l_run + g_proj[row*64 + t];
        float s1 = y, s2 = y*y;
        #pragma unroll
        for (int off = 16; off; off >>= 1) {
            s1 += __shfl_xor_sync(0xffffffffu, s1, off);
            s2 += __shfl_xor_sync(0xffffffffu, s2, off);
        }
        if (l == 0) { red[w*2] = s1; red[w*2 + 1] = s2; }
    }
    __syncthreads();
    if (t < 64) {
        float s1 = red[0] + red[2];
        float s2 = red[1] + red[3];
        float mu  = s1 * (1.0f/64.0f);
        float var = s2 * (1.0f/64.0f) - mu*mu;
        out[row*64 + t] = gamma[t] * (y - mu) * rsqrtf(var + 1e-6f) + beta[t];
    }
}

// ---------------- launch -----------------------------------------------------
extern "C" void kernel_launch(void* const* d_in, const int* in_sizes, int n_in,
                              void* d_out, int out_size) {
    const float* x    = (const float*)d_in[0];
    const float* adj  = (const float*)d_in[1];
    const float* Wp   = (const float*)d_in[2];
    const float* bp   = (const float*)d_in[3];
    const float* Wq1  = (const float*)d_in[4];
    const float* bq1  = (const float*)d_in[5];
    const float* Wk1  = (const float*)d_in[6];
    const float* bk1  = (const float*)d_in[7];
    const float* Wv1  = (const float*)d_in[8];
    const float* bv1  = (const float*)d_in[9];
    const float* Wq2  = (const float*)d_in[10];
    const float* bq2  = (const float*)d_in[11];
    const float* Wk2  = (const float*)d_in[12];
    const float* bk2  = (const float*)d_in[13];
    const float* Wv2  = (const float*)d_in[14];
    const float* bv2  = (const float*)d_in[15];
    const float* gamma= (const float*)d_in[16];
    const float* beta = (const float*)d_in[17];
    float* out = (float*)d_out;

    build_csr<<<NN, 256>>>(adj);
    linear1<<<ROWS/RPB1, 448>>>(x, Wp, bp, Wq1, bq1, Wk1, bk1, Wv1, bv1);
    gat1<<<ROWS, 128>>>();
    linear2<<<ROWS/RPB2, 192>>>(Wq2, bq2, Wk2, bk2, Wv2, bv2);
    gat2_ln<<<ROWS, 128>>>(gamma, beta, out);
}

// round 8
// speedup vs baseline: 1.0018x; 1.0018x over previous
#include <cuda_runtime.h>
#include <math.h>

#define NB 4
#define NN 2048
#define FIN 32
#define DD 64
#define MAXNB 512
#define ROWS (NB*NN)

// ---------------- scratch (device globals; no allocation allowed) ----------
__device__ int   g_cnt[NN];
__device__ int   g_cols[NN*MAXNB];
__device__ float g_proj[ROWS*DD];
__device__ float g_q1[ROWS*128];
__device__ float g_k1[ROWS*128];
__device__ float g_v1[ROWS*128];
__device__ float g_h1[ROWS*128];
__device__ float g_q2[ROWS*64];
__device__ float g_k2[ROWS*64];
__device__ float g_v2[ROWS*64];

// ---------------- kernel 1: deterministic CSR build ------------------------
__global__ __launch_bounds__(256, 4)
void build_csr(const float* __restrict__ adj) {
    int r = blockIdx.x;               // node row
    int t = threadIdx.x;              // 256 threads
    int w = t >> 5, l = t & 31;
    __shared__ int wcnt[8];
    int base = 0;
    for (int c0 = 0; c0 < NN; c0 += 256) {
        int col = c0 + t;
        bool pred = (adj[r*NN + col] != 0.0f);
        unsigned m = __ballot_sync(0xffffffffu, pred);
        if (l == 0) wcnt[w] = __popc(m);
        __syncthreads();
        int pre = 0, tot = 0;
        #pragma unroll
        for (int k = 0; k < 8; k++) { if (k < w) pre += wcnt[k]; tot += wcnt[k]; }
        int pos = base + pre + __popc(m & ((1u << l) - 1u));
        if (pred && pos < MAXNB) g_cols[r*MAXNB + pos] = col;
        base += tot;
        __syncthreads();
    }
    if (t == 0) g_cnt[r] = (base < MAXNB) ? base : MAXNB;
}

// ---- kernel 2: fused linear1 (proj + q1/k1/v1), register-tiled 8x4 --------
// 16 rows/block, 224 threads: thread = (colgroup cg = t>>1, rowgroup rg = t&1)
// cg<16 -> Wp, cg<48 -> Wq1, cg<80 -> Wk1, else Wv1. Each thread: 8 rows x 4 cols.
#define RPB1 16
__global__ __launch_bounds__(224)
void linear1(const float* __restrict__ x,
             const float* __restrict__ Wp,  const float* __restrict__ bp,
             const float* __restrict__ Wq1, const float* __restrict__ bq1,
             const float* __restrict__ Wk1, const float* __restrict__ bk1,
             const float* __restrict__ Wv1, const float* __restrict__ bv1) {
    int row0 = blockIdx.x * RPB1;
    int t = threadIdx.x;              // 224
    __shared__ float xsT[FIN*20];     // k-major, padded: xsT[k*20 + r]
    for (int i = t; i < RPB1*FIN; i += 224) {
        int r = i >> 5, k = i & 31;   // coalesced global read
        xsT[k*20 + r] = x[row0*FIN + i];
    }
    __syncthreads();

    int cg = t >> 1, rg = t & 1;
    int rbase = rg * 8;
    const float* W; const float* bi; float* dst; int c0, nc;
    if (cg < 16)      { W = Wp;  bi = bp;  dst = g_proj; c0 = cg*4;        nc = 64;  }
    else if (cg < 48) { W = Wq1; bi = bq1; dst = g_q1;   c0 = (cg-16)*4;   nc = 128; }
    else if (cg < 80) { W = Wk1; bi = bk1; dst = g_k1;   c0 = (cg-48)*4;   nc = 128; }
    else              { W = Wv1; bi = bv1; dst = g_v1;   c0 = (cg-80)*4;   nc = 128; }

    float acc[8][4];
    float4 b4 = *(const float4*)(bi + c0);
    #pragma unroll
    for (int r = 0; r < 8; r++) {
        acc[r][0] = b4.x; acc[r][1] = b4.y; acc[r][2] = b4.z; acc[r][3] = b4.w;
    }

    #pragma unroll 8
    for (int k = 0; k < FIN; k++) {
        float4 w4 = *(const float4*)(W + k*nc + c0);
        const float* hk = xsT + k*20 + rbase;
        float4 h0 = *(const float4*)(hk);
        float4 h1 = *(const float4*)(hk + 4);
        float hr[8] = {h0.x, h0.y, h0.z, h0.w, h1.x, h1.y, h1.z, h1.w};
        float wv[4] = {w4.x, w4.y, w4.z, w4.w};
        #pragma unroll
        for (int r = 0; r < 8; r++)
            #pragma unroll
            for (int j = 0; j < 4; j++) acc[r][j] += hr[r] * wv[j];
    }

    #pragma unroll
    for (int r = 0; r < 8; r++) {
        float4 o; o.x = acc[r][0]; o.y = acc[r][1]; o.z = acc[r][2]; o.w = acc[r][3];
        *(float4*)(dst + (row0 + rbase + r)*nc + c0) = o;
    }
}

// ---------------- kernel 3: GAT1 sparse attention (4 heads, d=32) ----------
__global__ __launch_bounds__(128, 8)
void gat1(void) {
    int row = blockIdx.x;             // b*N+i
    int b = row >> 11, i = row & (NN - 1);
    int t = threadIdx.x;              // 128
    int w = t >> 5, l = t & 31;

    __shared__ float sc[4*MAXNB];
    __shared__ int   cols_s[MAXNB];
    __shared__ float m_run[4], l_run[4], factor_s[4];

    // lane l covers dims 4l..4l+3 (head = l>>3)
    float4 q4 = __ldg(((const float4*)(g_q1 + row*128)) + l);
    if (t < 4) { m_run[t] = -1e30f; l_run[t] = 0.0f; }

    int cnt = g_cnt[i];
    bool dense = (cnt == 0);
    int total = dense ? NN : cnt;
    const float SC1 = 0.17677669529663689f;  // 1/sqrt(32)
    float acc = 0.0f;

    for (int cs = 0; cs < total; cs += MAXNB) {
        int clen = min(MAXNB, total - cs);
        for (int idx = t; idx < clen; idx += 128)
            cols_s[idx] = dense ? (cs + idx) : g_cols[i*MAXNB + cs + idx];
        __syncthreads();

        // phase A: warp w handles neighbors w, w+4, ...; 4 heads via 8-lane segments
        #pragma unroll 2
        for (int idx = w; idx < clen; idx += 4) {
            const float4* kr = (const float4*)(g_k1 + (b*NN + cols_s[idx])*128);
            float4 k4 = __ldg(kr + l);
            float p = q4.x*k4.x + q4.y*k4.y + q4.z*k4.z + q4.w*k4.w;
            p += __shfl_down_sync(0xffffffffu, p, 4);
            p += __shfl_down_sync(0xffffffffu, p, 2);
            p += __shfl_down_sync(0xffffffffu, p, 1);
            if ((l & 7) == 0) sc[(l >> 3)*MAXNB + idx] = p * SC1;
        }
        __syncthreads();

        // phase B1: warp w = head w online-softmax stats
        {
            float mc = -1e30f;
            for (int idx = l; idx < clen; idx += 32)
                mc = fmaxf(mc, sc[w*MAXNB + idx]);
            #pragma unroll
            for (int off = 16; off; off >>= 1)
                mc = fmaxf(mc, __shfl_xor_sync(0xffffffffu, mc, off));
            float mo = m_run[w];
            float mn = fmaxf(mo, mc);
            float f  = __expf(mo - mn);
            float ls = 0.0f;
            for (int idx = l; idx < clen; idx += 32) {
                float p = __expf(sc[w*MAXNB + idx] - mn);
                sc[w*MAXNB + idx] = p;
                ls += p;
            }
            #pragma unroll
            for (int off = 16; off; off >>= 1)
                ls += __shfl_xor_sync(0xffffffffu, ls, off);
            if (l == 0) { m_run[w] = mn; l_run[w] = l_run[w]*f + ls; factor_s[w] = f; }
        }
        __syncthreads();

        // phase B2: thread t accumulates output dim t; 4-deep manual MLP
        {
            float f = factor_s[w];
            acc *= f;
            const float* vb = g_v1 + b*NN*128 + t;
            const float* scw = sc + w*MAXNB;
            int idx = 0;
            for (; idx + 4 <= clen; idx += 4) {
                int c0 = cols_s[idx], c1 = cols_s[idx+1];
                int c2 = cols_s[idx+2], c3 = cols_s[idx+3];
                float v0 = __ldg(vb + c0*128), v1 = __ldg(vb + c1*128);
                float v2 = __ldg(vb + c2*128), v3 = __ldg(vb + c3*128);
                acc += scw[idx]*v0 + scw[idx+1]*v1 + scw[idx+2]*v2 + scw[idx+3]*v3;
            }
            for (; idx < clen; idx++)
                acc += scw[idx] * __ldg(vb + cols_s[idx]*128);
        }
        __syncthreads();
    }
    g_h1[row*128 + t] = acc / l_run[w];
}

// ---- kernel 4: linear2 with fused ReLU, register-tiled 8x4 ------------------
// 16 rows/block, 96 threads: warp m -> {Wq2,Wk2,Wv2}; lane: cg = l>>1, rg = l&1
#define RPB2 16
__global__ __launch_bounds__(96)
void linear2(const float* __restrict__ Wq2, const float* __restrict__ bq2,
             const float* __restrict__ Wk2, const float* __restrict__ bk2,
             const float* __restrict__ Wv2, const float* __restrict__ bv2) {
    int row0 = blockIdx.x * RPB2;
    int t = threadIdx.x;              // 96
    __shared__ float hsT[128*20];     // k-major, padded: hsT[k*20 + r]
    for (int i = t; i < RPB2*128; i += 96) {
        int r = i >> 7, k = i & 127;  // coalesced global read; fused ReLU
        hsT[k*20 + r] = fmaxf(g_h1[row0*128 + i], 0.0f);
    }
    __syncthreads();

    int l = t & 31, m = t >> 5;
    int cg = l >> 1, rg = l & 1;
    int c0 = cg * 4, rbase = rg * 8;
    const float* W; const float* bi; float* dst;
    if (m == 0)      { W = Wq2; bi = bq2; dst = g_q2; }
    else if (m == 1) { W = Wk2; bi = bk2; dst = g_k2; }
    else             { W = Wv2; bi = bv2; dst = g_v2; }

    float acc[8][4];
    float4 b4 = *(const float4*)(bi + c0);
    #pragma unroll
    for (int r = 0; r < 8; r++) {
        acc[r][0] = b4.x; acc[r][1] = b4.y; acc[r][2] = b4.z; acc[r][3] = b4.w;
    }

    #pragma unroll 8
    for (int k = 0; k < 128; k++) {
        float4 w4 = *(const float4*)(W + k*64 + c0);
        const float* hk = hsT + k*20 + rbase;
        float4 h0 = *(const float4*)(hk);
        float4 h1 = *(const float4*)(hk + 4);
        float hr[8] = {h0.x, h0.y, h0.z, h0.w, h1.x, h1.y, h1.z, h1.w};
        float wv[4] = {w4.x, w4.y, w4.z, w4.w};
        #pragma unroll
        for (int r = 0; r < 8; r++)
            #pragma unroll
            for (int j = 0; j < 4; j++) acc[r][j] += hr[r] * wv[j];
    }

    #pragma unroll
    for (int r = 0; r < 8; r++) {
        float4 o; o.x = acc[r][0]; o.y = acc[r][1]; o.z = acc[r][2]; o.w = acc[r][3];
        *(float4*)(dst + (row0 + rbase + r)*64 + c0) = o;
    }
}

// ---------------- kernel 5: GAT2 (1 head, d=64) + residual + LayerNorm ------
__global__ __launch_bounds__(128, 8)
void gat2_ln(const float* __restrict__ gamma, const float* __restrict__ beta,
             float* __restrict__ out) {
    int row = blockIdx.x;             // b*N+i
    int b = row >> 11, i = row & (NN - 1);
    int t = threadIdx.x;              // 128
    int w = t >> 5, l = t & 31;
    int sub = l >> 4, ll = l & 15;    // 16-lane segments for scores
    int grp = t >> 6, d = t & 63;     // 2 neighbor-groups for V accumulation

    __shared__ float sc[MAXNB];
    __shared__ int   cols_s[MAXNB];
    __shared__ float m_run, l_run, factor_s;
    __shared__ float accs[128];
    __shared__ float red[4];

    // lane ll covers dims 4*ll..4*ll+3 of q (64 dims over 16 lanes)
    float4 q4 = __ldg(((const float4*)(g_q2 + row*64)) + ll);
    if (t == 0) { m_run = -1e30f; l_run = 0.0f; }

    int cnt = g_cnt[i];
    bool dense = (cnt == 0);
    int total = dense ? NN : cnt;
    float acc = 0.0f;

    for (int cs = 0; cs < total; cs += MAXNB) {
        int clen = min(MAXNB, total - cs);
        for (int idx = t; idx < clen; idx += 128)
            cols_s[idx] = dense ? (cs + idx) : g_cols[i*MAXNB + cs + idx];
        __syncthreads();

        // phase A: 8 neighbors per iteration (4 warps x 2 per warp)
        #pragma unroll 2
        for (int bidx = w*2; bidx < clen; bidx += 8) {
            int idx = bidx + sub;
            float p = 0.0f;
            if (idx < clen) {
                const float4* kr = (const float4*)(g_k2 + (b*NN + cols_s[idx])*64);
                float4 k4 = __ldg(kr + ll);
                p = q4.x*k4.x + q4.y*k4.y + q4.z*k4.z + q4.w*k4.w;
            }
            p += __shfl_down_sync(0xffffffffu, p, 8);
            p += __shfl_down_sync(0xffffffffu, p, 4);
            p += __shfl_down_sync(0xffffffffu, p, 2);
            p += __shfl_down_sync(0xffffffffu, p, 1);
            if (ll == 0 && idx < clen) sc[idx] = p * 0.125f;   // 1/sqrt(64)
        }
        __syncthreads();

        // phase B1: warp 0 online softmax stats
        if (w == 0) {
            float mc = -1e30f;
            for (int idx = l; idx < clen; idx += 32) mc = fmaxf(mc, sc[idx]);
            #pragma unroll
            for (int off = 16; off; off >>= 1)
                mc = fmaxf(mc, __shfl_xor_sync(0xffffffffu, mc, off));
            float mo = m_run;
            float mn = fmaxf(mo, mc);
            float f  = __expf(mo - mn);
            float ls = 0.0f;
            for (int idx = l; idx < clen; idx += 32) {
                float p = __expf(sc[idx] - mn);
                sc[idx] = p;
                ls += p;
            }
            #pragma unroll
            for (int off = 16; off; off >>= 1)
                ls += __shfl_xor_sync(0xffffffffu, ls, off);
            if (l == 0) { m_run = mn; l_run = l_run*f + ls; factor_s = f; }
        }
        __syncthreads();

        // phase B2: two 64-thread groups split neighbors (even/odd); MLP-4
        {
            float f = factor_s;
            acc *= f;
            const float* vb = g_v2 + b*NN*64 + d;
            int idx = grp;
            for (; idx + 8 <= clen + grp; idx += 8) {
                int c0 = cols_s[idx], c1 = cols_s[idx+2];
                int c2 = cols_s[idx+4], c3 = cols_s[idx+6];
                float v0 = __ldg(vb + c0*64), v1 = __ldg(vb + c1*64);
                float v2 = __ldg(vb + c2*64), v3 = __ldg(vb + c3*64);
                acc += sc[idx]*v0 + sc[idx+2]*v1 + sc[idx+4]*v2 + sc[idx+6]*v3;
            }
            for (; idx < clen; idx += 2)
                acc += sc[idx] * __ldg(vb + cols_s[idx]*64);
        }
        __syncthreads();
    }

    accs[t] = acc;
    __syncthreads();

    // residual + LayerNorm over 64
    float y = 0.0f;
    if (t < 64) {
        y = (accs[t] + accs[t + 64]) / l_run + g_proj[row*64 + t];
        float s1 = y, s2 = y*y;
        #pragma unroll
        for (int off = 16; off; off >>= 1) {
            s1 += __shfl_xor_sync(0xffffffffu, s1, off);
            s2 += __shfl_xor_sync(0xffffffffu, s2, off);
        }
        if (l == 0) { red[w*2] = s1; red[w*2 + 1] = s2; }
    }
    __syncthreads();
    if (t < 64) {
        float s1 = red[0] + red[2];
        float s2 = red[1] + red[3];
        float mu  = s1 * (1.0f/64.0f);
        float var = s2 * (1.0f/64.0f) - mu*mu;
        out[row*64 + t] = gamma[t] * (y - mu) * rsqrtf(var + 1e-6f) + beta[t];
    }
}

// ---------------- launch -----------------------------------------------------
extern "C" void kernel_launch(void* const* d_in, const int* in_sizes, int n_in,
                              void* d_out, int out_size) {
    const float* x    = (const float*)d_in[0];
    const float* adj  = (const float*)d_in[1];
    const float* Wp   = (const float*)d_in[2];
    const float* bp   = (const float*)d_in[3];
    const float* Wq1  = (const float*)d_in[4];
    const float* bq1  = (const float*)d_in[5];
    const float* Wk1  = (const float*)d_in[6];
    const float* bk1  = (const float*)d_in[7];
    const float* Wv1  = (const float*)d_in[8];
    const float* bv1  = (const float*)d_in[9];
    const float* Wq2  = (const float*)d_in[10];
    const float* bq2  = (const float*)d_in[11];
    const float* Wk2  = (const float*)d_in[12];
    const float* bk2  = (const float*)d_in[13];
    const float* Wv2  = (const float*)d_in[14];
    const float* bv2  = (const float*)d_in[15];
    const float* gamma= (const float*)d_in[16];
    const float* beta = (const float*)d_in[17];
    float* out = (float*)d_out;

    build_csr<<<NN, 256>>>(adj);
    linear1<<<ROWS/RPB1, 224>>>(x, Wp, bp, Wq1, bq1, Wk1, bk1, Wv1, bv1);
    gat1<<<ROWS, 128>>>();
    linear2<<<ROWS/RPB2, 96>>>(Wq2, bq2, Wk2, bk2, Wv2, bv2);
    gat2_ln<<<ROWS, 128>>>(gamma, beta, out);
}